// round 13
// baseline (speedup 1.0000x reference)
#include <cuda_runtime.h>
#include <cuda_fp16.h>
#include <math.h>
#include <stdint.h>

#define Bb 2
#define Nn 2048
#define Kk 48
#define Cc 128
#define NODES (Bb*Nn)          /* 4096 */
#define NTILES 2048            /* 2 nodes (96 edge-rows) per tile */
#define TILES_PER_CTA 4
#define EGRID (NTILES/TILES_PER_CTA)
#define EPSf 1e-5f
#define INV_SCALE (1.0f/30.0f)

// device scratch (no allocations allowed)
__device__ float g_hV1[NODES*Cc];
__device__ float g_hV2[NODES*Cc];
__device__ float g_P[NODES*Cc];
__device__ float g_Q[NODES*Cc];
__device__ __half g_Wimg[18*32768];          // 18 images x (hi 16384 + lo 16384)
__device__ __half g_XE[NTILES*12288];        // hE in fp16 swizzled tile format (50MB)
__device__ __half g_X [NTILES*12288];        // inter-layer activations (50MB)

// ---------------- helpers ---------------------------------------------------
static __device__ __forceinline__ float gelu_f(float x){
    return 0.5f * x * (1.0f + erff(x * 0.70710678118654752440f));
}
static __device__ __forceinline__ float warp_sum(float v){
    #pragma unroll
    for (int o = 16; o; o >>= 1) v += __shfl_xor_sync(0xffffffffu, v, o);
    return v;
}
static __device__ __forceinline__ uint32_t smem_u32(const void* p){
    uint32_t a;
    asm("{ .reg .u64 t; cvta.to.shared.u64 t, %1; cvt.u32.u64 %0, t; }" : "=r"(a) : "l"(p));
    return a;
}
static __device__ __forceinline__ void ldsm4(uint32_t* r, uint32_t addr){
    asm volatile("ldmatrix.sync.aligned.m8n8.x4.shared.b16 {%0,%1,%2,%3}, [%4];"
        : "=r"(r[0]), "=r"(r[1]), "=r"(r[2]), "=r"(r[3]) : "r"(addr));
}
static __device__ __forceinline__ void mma16816(float* c, const uint32_t* a, uint32_t b0, uint32_t b1){
    asm volatile("mma.sync.aligned.m16n8k16.row.col.f32.f16.f16.f32 "
        "{%0,%1,%2,%3},{%4,%5,%6,%7},{%8,%9},{%0,%1,%2,%3};"
        : "+f"(c[0]), "+f"(c[1]), "+f"(c[2]), "+f"(c[3])
        : "r"(a[0]), "r"(a[1]), "r"(a[2]), "r"(a[3]), "r"(b0), "r"(b1));
}
static __device__ __forceinline__ void cpa16(uint32_t saddr, const void* g){
    asm volatile("cp.async.cg.shared.global [%0], [%1], 16;" :: "r"(saddr), "l"(g));
}
#define CP_COMMIT() asm volatile("cp.async.commit_group;" ::: "memory")
#define CP_WAIT0()  asm volatile("cp.async.wait_group 0;" ::: "memory")

// swizzled byte offset inside a [rows x 128 fp16] tile (256B rows, 16B xor)
static __device__ __forceinline__ uint32_t sw_off(int row, int k){
    return (uint32_t)(row*256 + ((((k >> 3) ^ (row & 7))) << 4) + (k & 7)*2);
}
static __device__ __forceinline__ uint32_t pack_h(float a, float b){
    __half2 h = __floats2half2_rn(a, b);
    return *reinterpret_cast<uint32_t*>(&h);
}
static __device__ __forceinline__ void split_pair_h(float a, float b, uint32_t &hi, uint32_t &lo){
    __half2 H = __floats2half2_rn(a, b);
    float2 hf = __half22float2(H);
    hi = *reinterpret_cast<uint32_t*>(&H);
    lo = pack_h(a - hf.x, b - hf.y);
}

// warp GEMM: MT*16 rows x (NP*16) cols, K=128, fp16 2-term (A single, B hi+lo)
template<int NP, int MT>
static __device__ __forceinline__ void gemm_warp2(
    uint32_t su, uint32_t offA, uint32_t offBH, uint32_t offBL,
    const uint32_t* a_rbase, uint32_t a_rx, int a_k8, int b_nin, int b_k8, int ncol0,
    float (*acc)[4])
{
    #pragma unroll 1
    for (int ks = 0; ks < 8; ++ks){
        uint32_t ah[MT][4];
        uint32_t ak3 = (uint32_t)(ks*2 + a_k8);
        #pragma unroll
        for (int mi = 0; mi < MT; ++mi){
            uint32_t aoff = a_rbase[mi] + ((ak3 ^ a_rx) << 4);
            ldsm4(ah[mi], su + offA + aoff);
        }
        uint32_t bk3 = (uint32_t)(ks*2 + b_k8);
        uint32_t boffs[NP];
        #pragma unroll
        for (int np = 0; np < NP; ++np){
            int brow = ncol0 + np*16 + b_nin;
            boffs[np] = (uint32_t)(brow*256) + ((bk3 ^ (uint32_t)(brow & 7)) << 4);
        }
        uint32_t bf[NP][4];
        #pragma unroll
        for (int np = 0; np < NP; ++np) ldsm4(bf[np], su + offBH + boffs[np]);
        #pragma unroll
        for (int np = 0; np < NP; ++np)
            #pragma unroll
            for (int mi = 0; mi < MT; ++mi){
                mma16816(acc[mi*2*NP + 2*np],     ah[mi], bf[np][0], bf[np][1]);
                mma16816(acc[mi*2*NP + 2*np + 1], ah[mi], bf[np][2], bf[np][3]);
            }
        #pragma unroll
        for (int np = 0; np < NP; ++np) ldsm4(bf[np], su + offBL + boffs[np]);
        #pragma unroll
        for (int np = 0; np < NP; ++np)
            #pragma unroll
            for (int mi = 0; mi < MT; ++mi){
                mma16816(acc[mi*2*NP + 2*np],     ah[mi], bf[np][0], bf[np][1]);
                mma16816(acc[mi*2*NP + 2*np + 1], ah[mi], bf[np][2], bf[np][3]);
            }
    }
}

// ===================== weight prep: 18 transposed split images ==============
__global__ void __launch_bounds__(256) prep_w(
    const float* __restrict__ W1w,  const float* __restrict__ W2w,
    const float* __restrict__ W3w,  const float* __restrict__ W11w,
    const float* __restrict__ W12w, const float* __restrict__ W13w,
    const float* __restrict__ Winw, const float* __restrict__ Woutw)
{
    extern __shared__ float ws[];   // [128][128]
    const int b = blockIdx.x;
    const float* ptr; int ld = 128;
    switch (b){
        case 0: ptr = W1w + 128*128; break;
        case 1: ptr = W2w;  break;
        case 2: ptr = W3w;  break;
        case 3: ptr = W11w + 128*128; break;
        case 4: ptr = W12w; break;
        case 5: ptr = W13w; break;
        case 6: ptr = W1w;  break;
        case 7: ptr = W1w + 256*128; break;
        case 8: ptr = W11w; break;
        case 9: ptr = W11w + 256*128; break;
        case 10: case 11: case 12: case 13:
            ptr = Winw + (b - 10)*128; ld = 512; break;
        default: // 14..17
            ptr = Woutw + (size_t)(b - 14)*128*128; break;
    }
    const int t = threadIdx.x;
    for (int idx = t; idx < 4096; idx += 256){
        int k = idx >> 5, n4 = (idx & 31)*4;
        *(float4*)(ws + k*128 + n4) = *(const float4*)(ptr + (size_t)k*ld + n4);
    }
    __syncthreads();

    __half* hi = g_Wimg + (size_t)b * 32768;
    __half* lo = hi + 16384;
    for (int c = t; c < 2048; c += 256){
        int row = c >> 4;            // n
        int k0  = (c & 15) << 3;     // k
        union { uint32_t u[4]; uint4 q; } H, L;
        #pragma unroll
        for (int j = 0; j < 4; ++j){
            float w0 = ws[(k0 + 2*j    )*128 + row];
            float w1 = ws[(k0 + 2*j + 1)*128 + row];
            split_pair_h(w0, w1, H.u[j], L.u[j]);
        }
        uint32_t off = (uint32_t)(row*256 + (((k0 >> 3) ^ (row & 7)) << 4));
        *(uint4*)((char*)hi + off) = H.q;
        *(uint4*)((char*)lo + off) = L.q;
    }
}

// ===================== hE -> fp16 swizzled tile format ======================
__global__ void __launch_bounds__(192) conv_hE(const float* __restrict__ hE)
{
    const int blk = blockIdx.x;               // tile
    const int t = threadIdx.x;
    const float* src = hE + (size_t)blk*96*128;
    char* dst = (char*)(g_XE + (size_t)blk*12288);
    for (int c = t; c < 1536; c += 192){
        int row = c >> 4, k0 = (c & 15) << 3;
        const float4* s = (const float4*)(src + row*128 + k0);
        float4 v0 = s[0], v1 = s[1];
        union { uint32_t u[4]; uint4 q; } H;
        H.u[0] = pack_h(v0.x, v0.y);
        H.u[1] = pack_h(v0.z, v0.w);
        H.u[2] = pack_h(v1.x, v1.y);
        H.u[3] = pack_h(v1.z, v1.w);
        uint32_t off = (uint32_t)(row*256 + (((k0 >> 3) ^ (row & 7)) << 4));
        *(uint4*)(dst + off) = H.q;
    }
}

// ===================== node kernel: PQ (MODE 0) / FFN (MODE 1) ==============
// 16 rows per CTA, 128 threads (4 warps: warp = 16 rows x 32 cols, NP=2)
#define NODE_SMEM 90368
#define N_A  0u
#define N_H  4096u
#define N_BH 8192u
#define N_BL 40960u
#define N_SCR 73728u

template<int MODE>
__global__ void __launch_bounds__(128, 2) node_mma(
    const float* __restrict__ src,
    const __half* __restrict__ imgQ,
    const __half* __restrict__ imgP,
    const float* __restrict__ ba,
    const float* __restrict__ bout,
    const float* __restrict__ gam, const float* __restrict__ bet,
    const float* __restrict__ maskV,
    float* __restrict__ outQ, float* __restrict__ outP,
    float* __restrict__ outV)
{
    extern __shared__ char smc[];
    const uint32_t su = smem_u32(smc);
    const int t = threadIdx.x, lane = t & 31, w = t >> 5;
    const int blk = blockIdx.x;
    const int r0g = blk*16;

    const int ncol0 = w*32;
    const int qrow = lane >> 2, qcol = (lane & 3)*2;
    const int rowA = qrow, rowB = rowA + 8;
    const int sel = lane >> 3, la7 = lane & 7;
    const int a_row = la7 + ((sel & 1) << 3);
    uint32_t a_rbase[1] = { (uint32_t)(a_row*256) };
    const uint32_t a_rx = (uint32_t)(a_row & 7);
    const int a_k8 = sel >> 1;
    const int b_nin = la7 + ((sel >> 1) << 3);
    const int b_k8 = sel & 1;

    for (int c = t; c < 256; c += 128){
        int row = c >> 4, k0 = (c & 15) << 3;
        const float4* s = (const float4*)(src + (size_t)(r0g + row)*128 + k0);
        float4 v0 = s[0], v1 = s[1];
        union { uint32_t u[4]; uint4 q; } H;
        H.u[0] = pack_h(v0.x, v0.y);
        H.u[1] = pack_h(v0.z, v0.w);
        H.u[2] = pack_h(v1.x, v1.y);
        H.u[3] = pack_h(v1.z, v1.w);
        uint32_t off = (uint32_t)(row*256 + (((k0 >> 3) ^ (row & 7)) << 4));
        *(uint4*)(smc + N_A + off) = H.q;
    }

    if (MODE == 0){
        #pragma unroll 1
        for (int m = 0; m < 2; ++m){
            __syncthreads();
            const __half* img = m ? imgP : imgQ;
            {
                const uint4* sH = (const uint4*)img;
                const uint4* sL = sH + 2048;
                uint4* dH = (uint4*)(smc + N_BH);
                uint4* dL = (uint4*)(smc + N_BL);
                #pragma unroll
                for (int i = 0; i < 16; ++i){ dH[t + i*128] = sH[t + i*128]; dL[t + i*128] = sL[t + i*128]; }
            }
            __syncthreads();
            float acc[4][4];
            #pragma unroll
            for (int i = 0; i < 4; ++i){
                if (m == 0){
                    float2 b2 = *(const float2*)(ba + ncol0 + i*8 + qcol);
                    acc[i][0] = b2.x; acc[i][1] = b2.y; acc[i][2] = b2.x; acc[i][3] = b2.y;
                } else {
                    acc[i][0] = acc[i][1] = acc[i][2] = acc[i][3] = 0.f;
                }
            }
            gemm_warp2<2,1>(su, N_A, N_BH, N_BL, a_rbase, a_rx, a_k8, b_nin, b_k8, ncol0, acc);
            float* dst = m ? outP : outQ;
            #pragma unroll
            for (int i = 0; i < 4; ++i){
                int n = ncol0 + i*8 + qcol;
                *(float2*)(dst + (size_t)(r0g + rowA)*128 + n) = make_float2(acc[i][0], acc[i][1]);
                *(float2*)(dst + (size_t)(r0g + rowB)*128 + n) = make_float2(acc[i][2], acc[i][3]);
            }
        }
    } else {
        float out_acc[4][4];
        #pragma unroll
        for (int i = 0; i < 4; ++i){
            float2 b2 = *(const float2*)(bout + ncol0 + i*8 + qcol);
            out_acc[i][0] = b2.x; out_acc[i][1] = b2.y;
            out_acc[i][2] = b2.x; out_acc[i][3] = b2.y;
        }
        #pragma unroll 1
        for (int c = 0; c < 4; ++c){
            __syncthreads();
            {
                const uint4* sH = (const uint4*)(imgQ + (size_t)c*32768);
                const uint4* sL = sH + 2048;
                uint4* dH = (uint4*)(smc + N_BH);
                uint4* dL = (uint4*)(smc + N_BL);
                #pragma unroll
                for (int i = 0; i < 16; ++i){ dH[t + i*128] = sH[t + i*128]; dL[t + i*128] = sL[t + i*128]; }
            }
            __syncthreads();
            float h_acc[4][4];
            #pragma unroll
            for (int i = 0; i < 4; ++i){
                float2 b2 = *(const float2*)(ba + c*128 + ncol0 + i*8 + qcol);
                h_acc[i][0] = b2.x; h_acc[i][1] = b2.y;
                h_acc[i][2] = b2.x; h_acc[i][3] = b2.y;
            }
            gemm_warp2<2,1>(su, N_A, N_BH, N_BL, a_rbase, a_rx, a_k8, b_nin, b_k8, ncol0, h_acc);
            #pragma unroll
            for (int i = 0; i < 4; ++i){
                int n = ncol0 + i*8 + qcol;
                uint32_t hA = pack_h(gelu_f(h_acc[i][0]), gelu_f(h_acc[i][1]));
                uint32_t hB = pack_h(gelu_f(h_acc[i][2]), gelu_f(h_acc[i][3]));
                *(uint32_t*)(smc + N_H + sw_off(rowA, n)) = hA;
                *(uint32_t*)(smc + N_H + sw_off(rowB, n)) = hB;
            }
            __syncthreads();
            {
                const uint4* sH = (const uint4*)(imgP + (size_t)c*32768);
                const uint4* sL = sH + 2048;
                uint4* dH = (uint4*)(smc + N_BH);
                uint4* dL = (uint4*)(smc + N_BL);
                #pragma unroll
                for (int i = 0; i < 16; ++i){ dH[t + i*128] = sH[t + i*128]; dL[t + i*128] = sL[t + i*128]; }
            }
            __syncthreads();
            gemm_warp2<2,1>(su, N_H, N_BH, N_BL, a_rbase, a_rx, a_k8, b_nin, b_k8, ncol0, out_acc);
        }
        __syncthreads();
        float* scr = (float*)(smc + N_SCR);   // [16][132]
        #pragma unroll
        for (int i = 0; i < 4; ++i){
            int n = ncol0 + i*8 + qcol;
            float2 rA = *(const float2*)(src + (size_t)(r0g + rowA)*128 + n);
            float2 rB = *(const float2*)(src + (size_t)(r0g + rowB)*128 + n);
            scr[rowA*132 + n]     = rA.x + out_acc[i][0];
            scr[rowA*132 + n + 1] = rA.y + out_acc[i][1];
            scr[rowB*132 + n]     = rB.x + out_acc[i][2];
            scr[rowB*132 + n + 1] = rB.y + out_acc[i][3];
        }
        __syncthreads();
        #pragma unroll 1
        for (int r8 = 0; r8 < 4; ++r8){
            int r = w*4 + r8;
            int node = r0g + r;
            float x0 = scr[r*132 + lane],      x1 = scr[r*132 + lane + 32];
            float x2 = scr[r*132 + lane + 64], x3 = scr[r*132 + lane + 96];
            float s = warp_sum(x0 + x1 + x2 + x3);
            float q = warp_sum(x0*x0 + x1*x1 + x2*x2 + x3*x3);
            float mean = s * 0.0078125f;
            float var  = q * 0.0078125f - mean*mean;
            float rs = rsqrtf(var + EPSf);
            float mv = maskV[node];
            float y0 = mv*(gam[lane]     *(x0 - mean)*rs + bet[lane]);
            float y1 = mv*(gam[lane + 32]*(x1 - mean)*rs + bet[lane + 32]);
            float y2 = mv*(gam[lane + 64]*(x2 - mean)*rs + bet[lane + 64]);
            float y3 = mv*(gam[lane + 96]*(x3 - mean)*rs + bet[lane + 96]);
            float* o = outV + (size_t)node*128;
            o[lane] = y0; o[lane+32] = y1; o[lane+64] = y2; o[lane+96] = y3;
            float* g = g_hV2 + (size_t)node*128;
            g[lane] = y0; g[lane+32] = y1; g[lane+64] = y2; g[lane+96] = y3;
        }
    }
}

// ======================= edge layer kernels =================================
// LAYER 0: A=g_XE, init=Q+P preadd, out=gelu -> g_X
// LAYER 1: A=g_X,  init=bias,       out=gelu -> g_X (in-place per tile)
// LAYER 2: A=g_X,  init=bias,       out=epilogue (MODE0 node LN; MODE1 edge LN)
// LAYER 0/1: double-buffered A via cp.async: A0|A1|BH|BL = 114688 B
// LAYER 2: single A: A0|BH|BL|SCR = 98304 B
#define EL_SMEM01 114688
#define EL_SMEM2  98304
#define EL2_SCR   90112u

template<int LAYER, int MODE>
__global__ void __launch_bounds__(192, 2) edge_layer(
    const __half* __restrict__ Asrc,
    __half* __restrict__ Xout,
    const float* __restrict__ hE,
    const int*   __restrict__ Eidx,
    const float* __restrict__ maskA,
    const __half* __restrict__ Wimg,
    const float* __restrict__ bias,
    const float* __restrict__ residV,
    const float* __restrict__ gam, const float* __restrict__ bet,
    float* __restrict__ outp)
{
    extern __shared__ char smc[];
    const uint32_t su = smem_u32(smc);
    const uint32_t OFF_A0 = 0u;
    const uint32_t OFF_A1 = 24576u;                       // used only LAYER<2
    const uint32_t OFF_BH = (LAYER < 2) ? 49152u : 24576u;
    const uint32_t OFF_BL = OFF_BH + 32768u;

    const int t = threadIdx.x, lane = t & 31, wid = t >> 5;
    const int tile0 = blockIdx.x * TILES_PER_CTA;

    // ---- stage B once ------------------------------------------------------
    {
        const uint4* sH = (const uint4*)Wimg;
        const uint4* sL = sH + 2048;
        uint4* dH = (uint4*)(smc + OFF_BH);
        uint4* dL = (uint4*)(smc + OFF_BL);
        for (int i = t; i < 2048; i += 192){ dH[i] = sH[i]; dL[i] = sL[i]; }
    }
    // ---- prefetch A tile0 --------------------------------------------------
    {
        const uint4* src = (const uint4*)(Asrc + (size_t)tile0*12288);
        #pragma unroll
        for (int j = 0; j < 8; ++j)
            cpa16(su + OFF_A0 + (uint32_t)(t + j*192)*16u, src + t + j*192);
        CP_COMMIT();
    }

    // warp geometry: warp tile 32 rows x 64 cols
    const int rgrp = wid >> 1, cgrp = wid & 1;
    const int m0 = rgrp*32, ncol0 = cgrp*64;
    const int qrow = lane >> 2, qcol = (lane & 3)*2;
    const int sel = lane >> 3, la7 = lane & 7;
    const int a_row0 = m0 + la7 + ((sel & 1) << 3);
    uint32_t a_rbase[2] = { (uint32_t)(a_row0*256), (uint32_t)((a_row0 + 16)*256) };
    const uint32_t a_rx = (uint32_t)(a_row0 & 7);
    const int a_k8 = sel >> 1;
    const int b_nin = la7 + ((sel >> 1) << 3);
    const int b_k8 = sel & 1;

    float acc[16][4];

    #pragma unroll 1
    for (int it = 0; it < TILES_PER_CTA; ++it){
        const int tile = tile0 + it;
        const int node0 = tile*2;
        const int nbase = (node0 >> 11) << 11;
        const uint32_t acur = (LAYER < 2) ? ((it & 1) ? OFF_A1 : OFF_A0) : OFF_A0;

        CP_WAIT0();
        __syncthreads();                       // A[cur] visible; all prior reads done

        if (LAYER < 2 && it + 1 < TILES_PER_CTA){
            const uint32_t anext = ((it + 1) & 1) ? OFF_A1 : OFF_A0;
            const uint4* src = (const uint4*)(Asrc + (size_t)(tile + 1)*12288);
            #pragma unroll
            for (int j = 0; j < 8; ++j)
                cpa16(su + anext + (uint32_t)(t + j*192)*16u, src + t + j*192);
            CP_COMMIT();
        }

        // ---- init accumulators --------------------------------------------
        if (LAYER == 0){
            #pragma unroll
            for (int mi = 0; mi < 2; ++mi){
                int r0 = m0 + mi*16 + qrow, r1 = r0 + 8;
                int i0 = Eidx[(size_t)tile*96 + r0];
                int i1 = Eidx[(size_t)tile*96 + r1];
                const float* q0 = g_Q + (size_t)(node0 + r0/48)*128;
                const float* p0 = g_P + (size_t)(nbase + i0)*128;
                const float* q1 = g_Q + (size_t)(node0 + r1/48)*128;
                const float* p1 = g_P + (size_t)(nbase + i1)*128;
                #pragma unroll
                for (int ni = 0; ni < 8; ++ni){
                    int n = ncol0 + ni*8 + qcol;
                    float2 qa = *(const float2*)(q0 + n), pa = *(const float2*)(p0 + n);
                    float2 qb = *(const float2*)(q1 + n), pb = *(const float2*)(p1 + n);
                    acc[mi*8+ni][0] = qa.x + pa.x; acc[mi*8+ni][1] = qa.y + pa.y;
                    acc[mi*8+ni][2] = qb.x + pb.x; acc[mi*8+ni][3] = qb.y + pb.y;
                }
            }
        } else {
            #pragma unroll
            for (int mi = 0; mi < 2; ++mi)
                #pragma unroll
                for (int ni = 0; ni < 8; ++ni){
                    float2 b2 = *(const float2*)(bias + ncol0 + ni*8 + qcol);
                    acc[mi*8+ni][0] = b2.x; acc[mi*8+ni][1] = b2.y;
                    acc[mi*8+ni][2] = b2.x; acc[mi*8+ni][3] = b2.y;
                }
        }

        gemm_warp2<4,2>(su, acur, OFF_BH, OFF_BL, a_rbase, a_rx, a_k8, b_nin, b_k8, ncol0, acc);

        if (LAYER < 2){
            // gelu -> fp16 into A[cur] (dead after gemm), then copy to g_X
            __syncthreads();                   // all warps done reading A[cur]
            #pragma unroll
            for (int mi = 0; mi < 2; ++mi){
                int r0 = m0 + mi*16 + qrow, r1 = r0 + 8;
                #pragma unroll
                for (int ni = 0; ni < 8; ++ni){
                    int n = ncol0 + ni*8 + qcol;
                    uint32_t hA = pack_h(gelu_f(acc[mi*8+ni][0]), gelu_f(acc[mi*8+ni][1]));
                    uint32_t hB = pack_h(gelu_f(acc[mi*8+ni][2]), gelu_f(acc[mi*8+ni][3]));
                    *(uint32_t*)(smc + acur + sw_off(r0, n)) = hA;
                    *(uint32_t*)(smc + acur + sw_off(r1, n)) = hB;
                }
            }
            __syncthreads();
            {
                uint4* dst = (uint4*)(Xout + (size_t)tile*12288);
                const uint4* s = (const uint4*)(smc + acur);
                #pragma unroll
                for (int j = 0; j < 8; ++j) dst[t + j*192] = s[t + j*192];
            }
        } else {
            // ---- LAYER 2 epilogues ---------------------------------------
            __syncthreads();                   // A reads done; issue prefetch
            if (it + 1 < TILES_PER_CTA){
                const uint4* src = (const uint4*)(Asrc + (size_t)(tile + 1)*12288);
                #pragma unroll
                for (int j = 0; j < 8; ++j)
                    cpa16(su + OFF_A0 + (uint32_t)(t + j*192)*16u, src + t + j*192);
                CP_COMMIT();
            }
            if (MODE == 0){
                // masked node-sum via per-warp partials, + resid, LN -> outp
                float* P   = (float*)(smc + EL2_SCR);             // [6][2][68]
                float* xs  = (float*)(smc + EL2_SCR + 3328u);     // [256]
                float* s_s = (float*)(smc + EL2_SCR + 4352u);     // [2][4]
                float* s_q = (float*)(smc + EL2_SCR + 4384u);     // [2][4]
                #pragma unroll
                for (int mi = 0; mi < 2; ++mi){
                    int r0 = m0 + mi*16 + qrow, r1 = r0 + 8;
                    float mv0 = maskA[(size_t)tile*96 + r0];
                    float mv1 = maskA[(size_t)tile*96 + r1];
                    #pragma unroll
                    for (int ni = 0; ni < 8; ++ni){
                        float p0 = mv0*acc[mi*8+ni][0] + mv1*acc[mi*8+ni][2];
                        float p1 = mv0*acc[mi*8+ni][1] + mv1*acc[mi*8+ni][3];
                        #pragma unroll
                        for (int o = 4; o <= 16; o <<= 1){
                            p0 += __shfl_xor_sync(0xffffffffu, p0, o);
                            p1 += __shfl_xor_sync(0xffffffffu, p1, o);
                        }
                        if (lane < 4){
                            int cin = ni*8 + qcol;
                            P[(wid*2 + mi)*68 + cin]     = p0;
                            P[(wid*2 + mi)*68 + cin + 1] = p1;
                        }
                    }
                }
                __syncthreads();
                for (int idx = t; idx < 256; idx += 192){
                    int nl = idx >> 7, c = idx & 127;
                    int chalf = c >> 6, cin = c & 63;
                    float s;
                    if (nl == 0){
                        s = P[((0*2+chalf)*2 + 0)*68 + cin]
                          + P[((0*2+chalf)*2 + 1)*68 + cin]
                          + P[((1*2+chalf)*2 + 0)*68 + cin];
                    } else {
                        s = P[((1*2+chalf)*2 + 1)*68 + cin]
                          + P[((2*2+chalf)*2 + 0)*68 + cin]
                          + P[((2*2+chalf)*2 + 1)*68 + cin];
                    }
                    float xv = residV[(size_t)(node0 + nl)*128 + c] + s * INV_SCALE;
                    xs[idx] = xv;
                    float ws = warp_sum(xv), wq = warp_sum(xv*xv);
                    if (lane == 0){ s_s[nl*4 + ((idx >> 5) & 3)] = ws; s_q[nl*4 + ((idx >> 5) & 3)] = wq; }
                }
                __syncthreads();
                for (int idx = t; idx < 256; idx += 192){
                    int nl = idx >> 7, c = idx & 127;
                    float mean = (s_s[nl*4] + s_s[nl*4+1] + s_s[nl*4+2] + s_s[nl*4+3]) * 0.0078125f;
                    float var  = (s_q[nl*4] + s_q[nl*4+1] + s_q[nl*4+2] + s_q[nl*4+3]) * 0.0078125f - mean*mean;
                    outp[(size_t)(node0 + nl)*128 + c] =
                        gam[c]*(xs[idx] - mean)*rsqrtf(var + EPSf) + bet[c];
                }
                __syncthreads();               // scratch safe for next tile
            } else {
                // per-edge LN(h_E + msg) -> outp
                float* sp = (float*)(smc + EL2_SCR);      // [96][2]
                float* sq = sp + 192;                     // [96][2]
                #pragma unroll
                for (int mi = 0; mi < 2; ++mi){
                    int r0 = m0 + mi*16 + qrow, r1 = r0 + 8;
                    const float* e0 = hE + ((size_t)tile*96 + r0)*128;
                    const float* e1 = hE + ((size_t)tile*96 + r1)*128;
                    float s0 = 0.f, q0 = 0.f, s1 = 0.f, q1 = 0.f;
                    #pragma unroll
                    for (int ni = 0; ni < 8; ++ni){
                        int n = ncol0 + ni*8 + qcol;
                        float2 ea = *(const float2*)(e0 + n);
                        float2 eb = *(const float2*)(e1 + n);
                        float v0 = ea.x + acc[mi*8+ni][0], v1 = ea.y + acc[mi*8+ni][1];
                        float v2 = eb.x + acc[mi*8+ni][2], v3 = eb.y + acc[mi*8+ni][3];
                        acc[mi*8+ni][0] = v0; acc[mi*8+ni][1] = v1;
                        acc[mi*8+ni][2] = v2; acc[mi*8+ni][3] = v3;
                        s0 += v0 + v1; q0 += v0*v0 + v1*v1;
                        s1 += v2 + v3; q1 += v2*v2 + v3*v3;
                    }
                    s0 += __shfl_xor_sync(0xffffffffu, s0, 1); s0 += __shfl_xor_sync(0xffffffffu, s0, 2);
                    q0 += __shfl_xor_sync(0xffffffffu, q0, 1); q0 += __shfl_xor_sync(0xffffffffu, q0, 2);
                    s1 += __shfl_xor_sync(0xffffffffu, s1, 1); s1 += __shfl_xor_sync(0xffffffffu, s1, 2);
                    q1 += __shfl_xor_sync(0xffffffffu, q1, 1); q1 += __shfl_xor_sync(0xffffffffu, q1, 2);
                    if ((lane & 3) == 0){
                        sp[r0*2 + cgrp] = s0; sq[r0*2 + cgrp] = q0;
                        sp[r1*2 + cgrp] = s1; sq[r1*2 + cgrp] = q1;
                    }
                }
                __syncthreads();
                #pragma unroll
                for (int mi = 0; mi < 2; ++mi){
                    int r0 = m0 + mi*16 + qrow, r1 = r0 + 8;
                    float mean0 = (sp[r0*2] + sp[r0*2+1]) * 0.0078125f;
                    float var0  = (sq[r0*2] + sq[r0*2+1]) * 0.0078125f - mean0*mean0;
                    float rs0 = rsqrtf(var0 + EPSf);
                    float mean1 = (sp[r1*2] + sp[r1*2+1]) * 0.0078125f;
                    float var1  = (sq[r1*2] + sq[r1*2+1]) * 0.0078125f - mean1*mean1;
                    float rs1 = rsqrtf(var1 + EPSf);
                    float* o0 = outp + ((size_t)tile*96 + r0)*128;
                    float* o1 = outp + ((size_t)tile*96 + r1)*128;
                    #pragma unroll
                    for (int ni = 0; ni < 8; ++ni){
                        int n = ncol0 + ni*8 + qcol;
                        float2 g = *(const float2*)(gam + n);
                        float2 b = *(const float2*)(bet + n);
                        float2 oA, oB;
                        oA.x = g.x*(acc[mi*8+ni][0] - mean0)*rs0 + b.x;
                        oA.y = g.y*(acc[mi*8+ni][1] - mean0)*rs0 + b.y;
                        oB.x = g.x*(acc[mi*8+ni][2] - mean1)*rs1 + b.x;
                        oB.y = g.y*(acc[mi*8+ni][3] - mean1)*rs1 + b.y;
                        *(float2*)(o0 + n) = oA;
                        *(float2*)(o1 + n) = oB;
                    }
                }
                __syncthreads();               // scratch safe for next tile
            }
        }
    }
}

// ---------------------------------------------------------------------------
extern "C" void kernel_launch(void* const* d_in, const int* in_sizes, int n_in,
                              void* d_out, int out_size)
{
    const float* hV    = (const float*)d_in[0];
    const float* hE    = (const float*)d_in[1];
    const int*   Eidx  = (const int*)  d_in[2];
    const float* maskV = (const float*)d_in[3];
    const float* maskA = (const float*)d_in[4];
    const float* W1w   = (const float*)d_in[5];  const float* W1b  = (const float*)d_in[6];
    const float* W2w   = (const float*)d_in[7];  const float* W2b  = (const float*)d_in[8];
    const float* W3w   = (const float*)d_in[9];  const float* W3b  = (const float*)d_in[10];
    const float* W11w  = (const float*)d_in[11]; const float* W11b = (const float*)d_in[12];
    const float* W12w  = (const float*)d_in[13]; const float* W12b = (const float*)d_in[14];
    const float* W13w  = (const float*)d_in[15]; const float* W13b = (const float*)d_in[16];
    const float* Winw  = (const float*)d_in[17]; const float* Winb = (const float*)d_in[18];
    const float* Woutw = (const float*)d_in[19]; const float* Woutb= (const float*)d_in[20];
    const float* g1    = (const float*)d_in[21]; const float* b1   = (const float*)d_in[22];
    const float* g2    = (const float*)d_in[23]; const float* b2   = (const float*)d_in[24];
    const float* g3    = (const float*)d_in[25]; const float* b3   = (const float*)d_in[26];

    float* out  = (float*)d_out;
    float* outV = out;
    float* outE = out + (size_t)NODES*Cc;

    float* hV1p; cudaGetSymbolAddress((void**)&hV1p, g_hV1);
    float* hV2p; cudaGetSymbolAddress((void**)&hV2p, g_hV2);
    float* gQp;  cudaGetSymbolAddress((void**)&gQp,  g_Q);
    float* gPp;  cudaGetSymbolAddress((void**)&gPp,  g_P);
    __half* wimg; cudaGetSymbolAddress((void**)&wimg, g_Wimg);
    __half* xep;  cudaGetSymbolAddress((void**)&xep,  g_XE);
    __half* xp;   cudaGetSymbolAddress((void**)&xp,   g_X);

    cudaFuncSetAttribute(prep_w,      cudaFuncAttributeMaxDynamicSharedMemorySize, 65536);
    cudaFuncSetAttribute(node_mma<0>, cudaFuncAttributeMaxDynamicSharedMemorySize, NODE_SMEM);
    cudaFuncSetAttribute(node_mma<1>, cudaFuncAttributeMaxDynamicSharedMemorySize, NODE_SMEM);
    cudaFuncSetAttribute(edge_layer<0,0>, cudaFuncAttributeMaxDynamicSharedMemorySize, EL_SMEM01);
    cudaFuncSetAttribute(edge_layer<1,0>, cudaFuncAttributeMaxDynamicSharedMemorySize, EL_SMEM01);
    cudaFuncSetAttribute(edge_layer<2,0>, cudaFuncAttributeMaxDynamicSharedMemorySize, EL_SMEM2);
    cudaFuncSetAttribute(edge_layer<2,1>, cudaFuncAttributeMaxDynamicSharedMemorySize, EL_SMEM2);

    prep_w<<<18, 256, 65536>>>(W1w, W2w, W3w, W11w, W12w, W13w, Winw, Woutw);
    conv_hE<<<NTILES, 192>>>(hE);

    // pass 1: node message
    node_mma<0><<<NODES/16, 128, NODE_SMEM>>>(
        hV, wimg + (size_t)6*32768, wimg + (size_t)7*32768,
        W1b, nullptr, nullptr, nullptr, nullptr, gQp, gPp, nullptr);
    edge_layer<0,0><<<EGRID, 192, EL_SMEM01>>>(
        xep, xp, hE, Eidx, maskA, wimg + (size_t)0*32768,
        nullptr, nullptr, nullptr, nullptr, nullptr);
    edge_layer<1,0><<<EGRID, 192, EL_SMEM01>>>(
        xp, xp, hE, Eidx, maskA, wimg + (size_t)1*32768,
        W2b, nullptr, nullptr, nullptr, nullptr);
    edge_layer<2,0><<<EGRID, 192, EL_SMEM2>>>(
        xp, nullptr, hE, Eidx, maskA, wimg + (size_t)2*32768,
        W3b, hV, g1, b1, hV1p);

    // FFN + LN2 + mask
    node_mma<1><<<NODES/16, 128, NODE_SMEM>>>(
        hV1p, wimg + (size_t)10*32768, wimg + (size_t)14*32768,
        Winb, Woutb, g2, b2, maskV, nullptr, nullptr, outV);

    // pass 2: edge update
    node_mma<0><<<NODES/16, 128, NODE_SMEM>>>(
        hV2p, wimg + (size_t)8*32768, wimg + (size_t)9*32768,
        W11b, nullptr, nullptr, nullptr, nullptr, gQp, gPp, nullptr);
    edge_layer<0,0><<<EGRID, 192, EL_SMEM01>>>(
        xep, xp, hE, Eidx, maskA, wimg + (size_t)3*32768,
        nullptr, nullptr, nullptr, nullptr, nullptr);
    edge_layer<1,0><<<EGRID, 192, EL_SMEM01>>>(
        xp, xp, hE, Eidx, maskA, wimg + (size_t)4*32768,
        W12b, nullptr, nullptr, nullptr, nullptr);
    edge_layer<2,1><<<EGRID, 192, EL_SMEM2>>>(
        xp, nullptr, hE, Eidx, maskA, wimg + (size_t)5*32768,
        W13b, nullptr, g3, b3, outE);
}

// round 15
// speedup vs baseline: 1.0932x; 1.0932x over previous
#include <cuda_runtime.h>
#include <cuda_fp16.h>
#include <math.h>
#include <stdint.h>

#define Bb 2
#define Nn 2048
#define Kk 48
#define Cc 128
#define NODES (Bb*Nn)          /* 4096 */
#define EPSf 1e-5f
#define INV_SCALE (1.0f/30.0f)

// device scratch (no allocations allowed)
__device__ float g_hV1[NODES*Cc];
__device__ float g_hV2[NODES*Cc];
__device__ float g_P[NODES*Cc];
__device__ float g_Q[NODES*Cc];
__device__ __half g_Wimg[18*32768];   // 18 images x (hi 16384 + lo 16384) fp16

// ---------------- helpers ---------------------------------------------------
static __device__ __forceinline__ float gelu_f(float x){
    return 0.5f * x * (1.0f + erff(x * 0.70710678118654752440f));
}
static __device__ __forceinline__ float warp_sum(float v){
    #pragma unroll
    for (int o = 16; o; o >>= 1) v += __shfl_xor_sync(0xffffffffu, v, o);
    return v;
}
static __device__ __forceinline__ uint32_t smem_u32(const void* p){
    uint32_t a;
    asm("{ .reg .u64 t; cvta.to.shared.u64 t, %1; cvt.u32.u64 %0, t; }" : "=r"(a) : "l"(p));
    return a;
}
static __device__ __forceinline__ void ldsm4(uint32_t* r, uint32_t addr){
    asm volatile("ldmatrix.sync.aligned.m8n8.x4.shared.b16 {%0,%1,%2,%3}, [%4];"
        : "=r"(r[0]), "=r"(r[1]), "=r"(r[2]), "=r"(r[3]) : "r"(addr));
}
static __device__ __forceinline__ void mma16816(float* c, const uint32_t* a, uint32_t b0, uint32_t b1){
    asm volatile("mma.sync.aligned.m16n8k16.row.col.f32.f16.f16.f32 "
        "{%0,%1,%2,%3},{%4,%5,%6,%7},{%8,%9},{%0,%1,%2,%3};"
        : "+f"(c[0]), "+f"(c[1]), "+f"(c[2]), "+f"(c[3])
        : "r"(a[0]), "r"(a[1]), "r"(a[2]), "r"(a[3]), "r"(b0), "r"(b1));
}
// swizzled byte offset inside a [rows x 128 fp16] tile (256B rows, 16B xor)
static __device__ __forceinline__ uint32_t sw_off(int row, int k){
    return (uint32_t)(row*256 + ((((k >> 3) ^ (row & 7))) << 4) + (k & 7)*2);
}
static __device__ __forceinline__ uint32_t pack_h(float a, float b){
    __half2 h = __floats2half2_rn(a, b);
    return *reinterpret_cast<uint32_t*>(&h);
}
static __device__ __forceinline__ void split_pair_h(float a, float b, uint32_t &hi, uint32_t &lo){
    __half2 H = __floats2half2_rn(a, b);
    float2 hf = __half22float2(H);
    hi = *reinterpret_cast<uint32_t*>(&H);
    lo = pack_h(a - hf.x, b - hf.y);
}

// warp GEMM: MT*16 rows x (NP*16) cols, K=128, fp16 2-term (A single, B hi+lo)
template<int NP, int MT>
static __device__ __forceinline__ void gemm_warp2(
    uint32_t su, uint32_t offA, uint32_t offBH, uint32_t offBL,
    const uint32_t* a_rbase, uint32_t a_rx, int a_k8, int b_nin, int b_k8, int ncol0,
    float (*acc)[4])
{
    #pragma unroll 1
    for (int ks = 0; ks < 8; ++ks){
        uint32_t ah[MT][4];
        uint32_t ak3 = (uint32_t)(ks*2 + a_k8);
        #pragma unroll
        for (int mi = 0; mi < MT; ++mi){
            uint32_t aoff = a_rbase[mi] + ((ak3 ^ a_rx) << 4);
            ldsm4(ah[mi], su + offA + aoff);
        }
        uint32_t bk3 = (uint32_t)(ks*2 + b_k8);
        uint32_t boffs[NP];
        #pragma unroll
        for (int np = 0; np < NP; ++np){
            int brow = ncol0 + np*16 + b_nin;
            boffs[np] = (uint32_t)(brow*256) + ((bk3 ^ (uint32_t)(brow & 7)) << 4);
        }
        uint32_t bf[NP][4];
        #pragma unroll
        for (int np = 0; np < NP; ++np) ldsm4(bf[np], su + offBH + boffs[np]);
        #pragma unroll
        for (int np = 0; np < NP; ++np)
            #pragma unroll
            for (int mi = 0; mi < MT; ++mi){
                mma16816(acc[mi*2*NP + 2*np],     ah[mi], bf[np][0], bf[np][1]);
                mma16816(acc[mi*2*NP + 2*np + 1], ah[mi], bf[np][2], bf[np][3]);
            }
        #pragma unroll
        for (int np = 0; np < NP; ++np) ldsm4(bf[np], su + offBL + boffs[np]);
        #pragma unroll
        for (int np = 0; np < NP; ++np)
            #pragma unroll
            for (int mi = 0; mi < MT; ++mi){
                mma16816(acc[mi*2*NP + 2*np],     ah[mi], bf[np][0], bf[np][1]);
                mma16816(acc[mi*2*NP + 2*np + 1], ah[mi], bf[np][2], bf[np][3]);
            }
    }
}

// ===================== weight prep: 18 transposed split images ==============
__global__ void __launch_bounds__(256) prep_w(
    const float* __restrict__ W1w,  const float* __restrict__ W2w,
    const float* __restrict__ W3w,  const float* __restrict__ W11w,
    const float* __restrict__ W12w, const float* __restrict__ W13w,
    const float* __restrict__ Winw, const float* __restrict__ Woutw)
{
    extern __shared__ float ws[];   // [128][128]
    const int b = blockIdx.x;
    const float* ptr; int ld = 128;
    switch (b){
        case 0: ptr = W1w + 128*128; break;
        case 1: ptr = W2w;  break;
        case 2: ptr = W3w;  break;
        case 3: ptr = W11w + 128*128; break;
        case 4: ptr = W12w; break;
        case 5: ptr = W13w; break;
        case 6: ptr = W1w;  break;
        case 7: ptr = W1w + 256*128; break;
        case 8: ptr = W11w; break;
        case 9: ptr = W11w + 256*128; break;
        case 10: case 11: case 12: case 13:
            ptr = Winw + (b - 10)*128; ld = 512; break;
        default: // 14..17
            ptr = Woutw + (size_t)(b - 14)*128*128; break;
    }
    const int t = threadIdx.x;
    for (int idx = t; idx < 4096; idx += 256){
        int k = idx >> 5, n4 = (idx & 31)*4;
        *(float4*)(ws + k*128 + n4) = *(const float4*)(ptr + (size_t)k*ld + n4);
    }
    __syncthreads();

    __half* hi = g_Wimg + (size_t)b * 32768;
    __half* lo = hi + 16384;
    for (int c = t; c < 2048; c += 256){
        int row = c >> 4;            // n
        int k0  = (c & 15) << 3;     // k
        union { uint32_t u[4]; uint4 q; } H, L;
        #pragma unroll
        for (int j = 0; j < 4; ++j){
            float w0 = ws[(k0 + 2*j    )*128 + row];
            float w1 = ws[(k0 + 2*j + 1)*128 + row];
            split_pair_h(w0, w1, H.u[j], L.u[j]);
        }
        uint32_t off = (uint32_t)(row*256 + (((k0 >> 3) ^ (row & 7)) << 4));
        *(uint4*)((char*)hi + off) = H.q;
        *(uint4*)((char*)lo + off) = L.q;
    }
}

// ===================== node kernel: PQ (MODE 0) / FFN (MODE 1) ==============
// 16 rows per CTA, 128 threads (4 warps: warp = 16 rows x 32 cols, NP=2)
#define NODE_SMEM 90368
#define N_A  0u
#define N_H  4096u
#define N_BH 8192u
#define N_BL 40960u
#define N_SCR 73728u

template<int MODE>
__global__ void __launch_bounds__(128, 2) node_mma(
    const float* __restrict__ src,
    const __half* __restrict__ imgQ,
    const __half* __restrict__ imgP,
    const float* __restrict__ ba,
    const float* __restrict__ bout,
    const float* __restrict__ gam, const float* __restrict__ bet,
    const float* __restrict__ maskV,
    float* __restrict__ outQ, float* __restrict__ outP,
    float* __restrict__ outV)
{
    extern __shared__ char smc[];
    const uint32_t su = smem_u32(smc);
    const int t = threadIdx.x, lane = t & 31, w = t >> 5;
    const int blk = blockIdx.x;
    const int r0g = blk*16;

    const int ncol0 = w*32;
    const int qrow = lane >> 2, qcol = (lane & 3)*2;
    const int rowA = qrow, rowB = rowA + 8;
    const int sel = lane >> 3, la7 = lane & 7;
    const int a_row = la7 + ((sel & 1) << 3);
    uint32_t a_rbase[1] = { (uint32_t)(a_row*256) };
    const uint32_t a_rx = (uint32_t)(a_row & 7);
    const int a_k8 = sel >> 1;
    const int b_nin = la7 + ((sel >> 1) << 3);
    const int b_k8 = sel & 1;

    for (int c = t; c < 256; c += 128){
        int row = c >> 4, k0 = (c & 15) << 3;
        const float4* s = (const float4*)(src + (size_t)(r0g + row)*128 + k0);
        float4 v0 = s[0], v1 = s[1];
        union { uint32_t u[4]; uint4 q; } H;
        H.u[0] = pack_h(v0.x, v0.y);
        H.u[1] = pack_h(v0.z, v0.w);
        H.u[2] = pack_h(v1.x, v1.y);
        H.u[3] = pack_h(v1.z, v1.w);
        uint32_t off = (uint32_t)(row*256 + (((k0 >> 3) ^ (row & 7)) << 4));
        *(uint4*)(smc + N_A + off) = H.q;
    }

    if (MODE == 0){
        #pragma unroll 1
        for (int m = 0; m < 2; ++m){
            __syncthreads();
            const __half* img = m ? imgP : imgQ;
            {
                const uint4* sH = (const uint4*)img;
                const uint4* sL = sH + 2048;
                uint4* dH = (uint4*)(smc + N_BH);
                uint4* dL = (uint4*)(smc + N_BL);
                #pragma unroll
                for (int i = 0; i < 16; ++i){ dH[t + i*128] = sH[t + i*128]; dL[t + i*128] = sL[t + i*128]; }
            }
            __syncthreads();
            float acc[4][4];
            #pragma unroll
            for (int i = 0; i < 4; ++i){
                if (m == 0){
                    float2 b2 = *(const float2*)(ba + ncol0 + i*8 + qcol);
                    acc[i][0] = b2.x; acc[i][1] = b2.y; acc[i][2] = b2.x; acc[i][3] = b2.y;
                } else {
                    acc[i][0] = acc[i][1] = acc[i][2] = acc[i][3] = 0.f;
                }
            }
            gemm_warp2<2,1>(su, N_A, N_BH, N_BL, a_rbase, a_rx, a_k8, b_nin, b_k8, ncol0, acc);
            float* dst = m ? outP : outQ;
            #pragma unroll
            for (int i = 0; i < 4; ++i){
                int n = ncol0 + i*8 + qcol;
                *(float2*)(dst + (size_t)(r0g + rowA)*128 + n) = make_float2(acc[i][0], acc[i][1]);
                *(float2*)(dst + (size_t)(r0g + rowB)*128 + n) = make_float2(acc[i][2], acc[i][3]);
            }
        }
    } else {
        float out_acc[4][4];
        #pragma unroll
        for (int i = 0; i < 4; ++i){
            float2 b2 = *(const float2*)(bout + ncol0 + i*8 + qcol);
            out_acc[i][0] = b2.x; out_acc[i][1] = b2.y;
            out_acc[i][2] = b2.x; out_acc[i][3] = b2.y;
        }
        #pragma unroll 1
        for (int c = 0; c < 4; ++c){
            __syncthreads();
            {
                const uint4* sH = (const uint4*)(imgQ + (size_t)c*32768);
                const uint4* sL = sH + 2048;
                uint4* dH = (uint4*)(smc + N_BH);
                uint4* dL = (uint4*)(smc + N_BL);
                #pragma unroll
                for (int i = 0; i < 16; ++i){ dH[t + i*128] = sH[t + i*128]; dL[t + i*128] = sL[t + i*128]; }
            }
            __syncthreads();
            float h_acc[4][4];
            #pragma unroll
            for (int i = 0; i < 4; ++i){
                float2 b2 = *(const float2*)(ba + c*128 + ncol0 + i*8 + qcol);
                h_acc[i][0] = b2.x; h_acc[i][1] = b2.y;
                h_acc[i][2] = b2.x; h_acc[i][3] = b2.y;
            }
            gemm_warp2<2,1>(su, N_A, N_BH, N_BL, a_rbase, a_rx, a_k8, b_nin, b_k8, ncol0, h_acc);
            #pragma unroll
            for (int i = 0; i < 4; ++i){
                int n = ncol0 + i*8 + qcol;
                uint32_t hA = pack_h(gelu_f(h_acc[i][0]), gelu_f(h_acc[i][1]));
                uint32_t hB = pack_h(gelu_f(h_acc[i][2]), gelu_f(h_acc[i][3]));
                *(uint32_t*)(smc + N_H + sw_off(rowA, n)) = hA;
                *(uint32_t*)(smc + N_H + sw_off(rowB, n)) = hB;
            }
            __syncthreads();
            {
                const uint4* sH = (const uint4*)(imgP + (size_t)c*32768);
                const uint4* sL = sH + 2048;
                uint4* dH = (uint4*)(smc + N_BH);
                uint4* dL = (uint4*)(smc + N_BL);
                #pragma unroll
                for (int i = 0; i < 16; ++i){ dH[t + i*128] = sH[t + i*128]; dL[t + i*128] = sL[t + i*128]; }
            }
            __syncthreads();
            gemm_warp2<2,1>(su, N_H, N_BH, N_BL, a_rbase, a_rx, a_k8, b_nin, b_k8, ncol0, out_acc);
        }
        __syncthreads();
        float* scr = (float*)(smc + N_SCR);   // [16][132]
        #pragma unroll
        for (int i = 0; i < 4; ++i){
            int n = ncol0 + i*8 + qcol;
            float2 rA = *(const float2*)(src + (size_t)(r0g + rowA)*128 + n);
            float2 rB = *(const float2*)(src + (size_t)(r0g + rowB)*128 + n);
            scr[rowA*132 + n]     = rA.x + out_acc[i][0];
            scr[rowA*132 + n + 1] = rA.y + out_acc[i][1];
            scr[rowB*132 + n]     = rB.x + out_acc[i][2];
            scr[rowB*132 + n + 1] = rB.y + out_acc[i][3];
        }
        __syncthreads();
        #pragma unroll 1
        for (int r8 = 0; r8 < 4; ++r8){
            int r = w*4 + r8;
            int node = r0g + r;
            float x0 = scr[r*132 + lane],      x1 = scr[r*132 + lane + 32];
            float x2 = scr[r*132 + lane + 64], x3 = scr[r*132 + lane + 96];
            float s = warp_sum(x0 + x1 + x2 + x3);
            float q = warp_sum(x0*x0 + x1*x1 + x2*x2 + x3*x3);
            float mean = s * 0.0078125f;
            float var  = q * 0.0078125f - mean*mean;
            float rs = rsqrtf(var + EPSf);
            float mv = maskV[node];
            float y0 = mv*(gam[lane]     *(x0 - mean)*rs + bet[lane]);
            float y1 = mv*(gam[lane + 32]*(x1 - mean)*rs + bet[lane + 32]);
            float y2 = mv*(gam[lane + 64]*(x2 - mean)*rs + bet[lane + 64]);
            float y3 = mv*(gam[lane + 96]*(x3 - mean)*rs + bet[lane + 96]);
            float* o = outV + (size_t)node*128;
            o[lane] = y0; o[lane+32] = y1; o[lane+64] = y2; o[lane+96] = y3;
            float* g = g_hV2 + (size_t)node*128;
            g[lane] = y0; g[lane+32] = y1; g[lane+64] = y2; g[lane+96] = y3;
        }
    }
}

// ======================= edge pass: 2 tiles (4 nodes, 192 rows) per CTA =====
// 192 threads / 6 warps (warp tile 32x64 within each 96-row tile).
// smem: A0 24KB | A1 24KB | BH 32KB | BL 32KB = 114688 B -> 2 CTAs/SM.
#define EDGE_SMEM 114688
#define E_A0 0u
#define E_A1 24576u
#define E_BH 49152u
#define E_BL 81920u

template<int MODE>
__global__ void __launch_bounds__(192, 2) edge_mma(
    const float* __restrict__ hE,
    const int*   __restrict__ Eidx,
    const float* __restrict__ maskA,
    const __half* __restrict__ Wimg,          // 3 layer slots x 32768 fp16
    const float* __restrict__ bb, const float* __restrict__ bc,
    const float* __restrict__ residV,
    const float* __restrict__ gam, const float* __restrict__ bet,
    float* __restrict__ outp)                 // MODE0: g_hV1 ; MODE1: outE
{
    extern __shared__ char smc[];
    const uint32_t su = smem_u32(smc);

    const int t = threadIdx.x, lane = t & 31, wid = t >> 5;
    const int blk = blockIdx.x;
    const int tileB = blk*2;                  // first of 2 tiles

    // ---- stage A0+A1 (192 hE rows, fp16) + B layer 0 -----------------------
    for (int c = t; c < 3072; c += 192){
        int row = c >> 4, k0 = (c & 15) << 3;
        const float4* s = (const float4*)(hE + ((size_t)tileB*96 + row)*128 + k0);
        float4 v0 = s[0], v1 = s[1];
        union { uint32_t u[4]; uint4 q; } H;
        H.u[0] = pack_h(v0.x, v0.y);
        H.u[1] = pack_h(v0.z, v0.w);
        H.u[2] = pack_h(v1.x, v1.y);
        H.u[3] = pack_h(v1.z, v1.w);
        int lrow = (row >= 96) ? (row - 96) : row;      // FIX: 96 not pow2
        uint32_t base = (row >= 96) ? E_A1 : E_A0;
        uint32_t off = (uint32_t)(lrow*256 + (((k0 >> 3) ^ (lrow & 7)) << 4));
        *(uint4*)(smc + base + off) = H.q;
    }
    {
        const uint4* sH = (const uint4*)Wimg;
        const uint4* sL = sH + 2048;
        uint4* dH = (uint4*)(smc + E_BH);
        uint4* dL = (uint4*)(smc + E_BL);
        for (int i = t; i < 2048; i += 192){ dH[i] = sH[i]; dL[i] = sL[i]; }
    }
    __syncthreads();

    // warp geometry: warp tile 32 rows x 64 cols
    const int rgrp = wid >> 1, cgrp = wid & 1;
    const int m0 = rgrp*32, ncol0 = cgrp*64;
    const int qrow = lane >> 2, qcol = (lane & 3)*2;
    const int sel = lane >> 3, la7 = lane & 7;
    const int a_row0 = m0 + la7 + ((sel & 1) << 3);
    uint32_t a_rbase[2] = { (uint32_t)(a_row0*256), (uint32_t)((a_row0 + 16)*256) };
    const uint32_t a_rx = (uint32_t)(a_row0 & 7);
    const int a_k8 = sel >> 1;
    const int b_nin = la7 + ((sel >> 1) << 3);
    const int b_k8 = sel & 1;

    float acc[16][4];

    #pragma unroll 1
    for (int l = 0; l < 3; ++l){
        #pragma unroll 1
        for (int tt = 0; tt < 2; ++tt){
            const int tile = tileB + tt;
            const int node0 = tile*2;
            const int nbase = (node0 >> 11) << 11;
            const uint32_t Aoff = tt ? E_A1 : E_A0;

            // ---- init accumulators ----------------------------------------
            if (l == 0){
                #pragma unroll
                for (int mi = 0; mi < 2; ++mi){
                    int r0 = m0 + mi*16 + qrow, r1 = r0 + 8;
                    int i0 = Eidx[(size_t)tile*96 + r0];
                    int i1 = Eidx[(size_t)tile*96 + r1];
                    const float* q0 = g_Q + (size_t)(node0 + r0/48)*128;
                    const float* p0 = g_P + (size_t)(nbase + i0)*128;
                    const float* q1 = g_Q + (size_t)(node0 + r1/48)*128;
                    const float* p1 = g_P + (size_t)(nbase + i1)*128;
                    #pragma unroll
                    for (int ni = 0; ni < 8; ++ni){
                        int n = ncol0 + ni*8 + qcol;
                        float2 qa = *(const float2*)(q0 + n), pa = *(const float2*)(p0 + n);
                        float2 qb = *(const float2*)(q1 + n), pb = *(const float2*)(p1 + n);
                        acc[mi*8+ni][0] = qa.x + pa.x; acc[mi*8+ni][1] = qa.y + pa.y;
                        acc[mi*8+ni][2] = qb.x + pb.x; acc[mi*8+ni][3] = qb.y + pb.y;
                    }
                }
            } else {
                const float* bias = (l == 1) ? bb : bc;
                #pragma unroll
                for (int mi = 0; mi < 2; ++mi)
                    #pragma unroll
                    for (int ni = 0; ni < 8; ++ni){
                        float2 b2 = *(const float2*)(bias + ncol0 + ni*8 + qcol);
                        acc[mi*8+ni][0] = b2.x; acc[mi*8+ni][1] = b2.y;
                        acc[mi*8+ni][2] = b2.x; acc[mi*8+ni][3] = b2.y;
                    }
            }

            gemm_warp2<4,2>(su, Aoff, E_BH, E_BL, a_rbase, a_rx, a_k8, b_nin, b_k8, ncol0, acc);

            if (l < 2){
                __syncthreads();         // all warps done reading A[tt] (and B for tt==1)
                // gelu -> fp16 back into A[tt]
                #pragma unroll
                for (int mi = 0; mi < 2; ++mi){
                    int r0 = m0 + mi*16 + qrow, r1 = r0 + 8;
                    #pragma unroll
                    for (int ni = 0; ni < 8; ++ni){
                        int n = ncol0 + ni*8 + qcol;
                        uint32_t hA = pack_h(gelu_f(acc[mi*8+ni][0]), gelu_f(acc[mi*8+ni][1]));
                        uint32_t hB = pack_h(gelu_f(acc[mi*8+ni][2]), gelu_f(acc[mi*8+ni][3]));
                        *(uint32_t*)(smc + Aoff + sw_off(r0, n)) = hA;
                        *(uint32_t*)(smc + Aoff + sw_off(r1, n)) = hB;
                    }
                }
                if (tt == 1){
                    // restage B for next layer (BH/BL reads all done)
                    const uint4* sH = (const uint4*)(Wimg + (size_t)(l + 1)*32768);
                    const uint4* sL = sH + 2048;
                    uint4* dH = (uint4*)(smc + E_BH);
                    uint4* dL = (uint4*)(smc + E_BL);
                    for (int i = t; i < 2048; i += 192){ dH[i] = sH[i]; dL[i] = sL[i]; }
                    __syncthreads();
                }
                // (tt==0: no sync needed; t1 gemm reads A1/B which are untouched)
            } else {
                // ================= final epilogue for this tile ==============
                __syncthreads();         // A[tt] reads done -> usable as scratch
                char* scr = smc + Aoff;
                if (MODE == 0){
                    float* P   = (float*)scr;              // [6][2][68]
                    float* xs  = (float*)(scr + 3328);     // [256]
                    float* s_s = (float*)(scr + 4352);     // [2][4]
                    float* s_q = (float*)(scr + 4384);     // [2][4]
                    #pragma unroll
                    for (int mi = 0; mi < 2; ++mi){
                        int r0 = m0 + mi*16 + qrow, r1 = r0 + 8;
                        float mv0 = maskA[(size_t)tile*96 + r0];
                        float mv1 = maskA[(size_t)tile*96 + r1];
                        #pragma unroll
                        for (int ni = 0; ni < 8; ++ni){
                            float p0 = mv0*acc[mi*8+ni][0] + mv1*acc[mi*8+ni][2];
                            float p1 = mv0*acc[mi*8+ni][1] + mv1*acc[mi*8+ni][3];
                            #pragma unroll
                            for (int o = 4; o <= 16; o <<= 1){
                                p0 += __shfl_xor_sync(0xffffffffu, p0, o);
                                p1 += __shfl_xor_sync(0xffffffffu, p1, o);
                            }
                            if (lane < 4){
                                int cin = ni*8 + qcol;
                                P[(wid*2 + mi)*68 + cin]     = p0;
                                P[(wid*2 + mi)*68 + cin + 1] = p1;
                            }
                        }
                    }
                    __syncthreads();
                    for (int idx = t; idx < 256; idx += 192){
                        int nl = idx >> 7, c = idx & 127;
                        int chalf = c >> 6, cin = c & 63;
                        float s;
                        if (nl == 0){
                            s = P[((0*2+chalf)*2 + 0)*68 + cin]
                              + P[((0*2+chalf)*2 + 1)*68 + cin]
                              + P[((1*2+chalf)*2 + 0)*68 + cin];
                        } else {
                            s = P[((1*2+chalf)*2 + 1)*68 + cin]
                              + P[((2*2+chalf)*2 + 0)*68 + cin]
                              + P[((2*2+chalf)*2 + 1)*68 + cin];
                        }
                        float xv = residV[(size_t)(node0 + nl)*128 + c] + s * INV_SCALE;
                        xs[idx] = xv;
                        float ws = warp_sum(xv), wq = warp_sum(xv*xv);
                        if (lane == 0){ s_s[nl*4 + ((idx >> 5) & 3)] = ws; s_q[nl*4 + ((idx >> 5) & 3)] = wq; }
                    }
                    __syncthreads();
                    for (int idx = t; idx < 256; idx += 192){
                        int nl = idx >> 7, c = idx & 127;
                        float mean = (s_s[nl*4] + s_s[nl*4+1] + s_s[nl*4+2] + s_s[nl*4+3]) * 0.0078125f;
                        float var  = (s_q[nl*4] + s_q[nl*4+1] + s_q[nl*4+2] + s_q[nl*4+3]) * 0.0078125f - mean*mean;
                        outp[(size_t)(node0 + nl)*128 + c] =
                            gam[c]*(xs[idx] - mean)*rsqrtf(var + EPSf) + bet[c];
                    }
                    __syncthreads();
                } else {
                    float* sp = (float*)scr;               // [96][2]
                    float* sq = sp + 192;                  // [96][2]
                    #pragma unroll
                    for (int mi = 0; mi < 2; ++mi){
                        int r0 = m0 + mi*16 + qrow, r1 = r0 + 8;
                        const float* e0 = hE + ((size_t)tile*96 + r0)*128;
                        const float* e1 = hE + ((size_t)tile*96 + r1)*128;
                        float s0 = 0.f, q0 = 0.f, s1 = 0.f, q1 = 0.f;
                        #pragma unroll
                        for (int ni = 0; ni < 8; ++ni){
                            int n = ncol0 + ni*8 + qcol;
                            float2 ea = *(const float2*)(e0 + n);
                            float2 eb = *(const float2*)(e1 + n);
                            float v0 = ea.x + acc[mi*8+ni][0], v1 = ea.y + acc[mi*8+ni][1];
                            float v2 = eb.x + acc[mi*8+ni][2], v3 = eb.y + acc[mi*8+ni][3];
                            acc[mi*8+ni][0] = v0; acc[mi*8+ni][1] = v1;
                            acc[mi*8+ni][2] = v2; acc[mi*8+ni][3] = v3;
                            s0 += v0 + v1; q0 += v0*v0 + v1*v1;
                            s1 += v2 + v3; q1 += v2*v2 + v3*v3;
                        }
                        s0 += __shfl_xor_sync(0xffffffffu, s0, 1); s0 += __shfl_xor_sync(0xffffffffu, s0, 2);
                        q0 += __shfl_xor_sync(0xffffffffu, q0, 1); q0 += __shfl_xor_sync(0xffffffffu, q0, 2);
                        s1 += __shfl_xor_sync(0xffffffffu, s1, 1); s1 += __shfl_xor_sync(0xffffffffu, s1, 2);
                        q1 += __shfl_xor_sync(0xffffffffu, q1, 1); q1 += __shfl_xor_sync(0xffffffffu, q1, 2);
                        if ((lane & 3) == 0){
                            sp[r0*2 + cgrp] = s0; sq[r0*2 + cgrp] = q0;
                            sp[r1*2 + cgrp] = s1; sq[r1*2 + cgrp] = q1;
                        }
                    }
                    __syncthreads();
                    #pragma unroll
                    for (int mi = 0; mi < 2; ++mi){
                        int r0 = m0 + mi*16 + qrow, r1 = r0 + 8;
                        float mean0 = (sp[r0*2] + sp[r0*2+1]) * 0.0078125f;
                        float var0  = (sq[r0*2] + sq[r0*2+1]) * 0.0078125f - mean0*mean0;
                        float rs0 = rsqrtf(var0 + EPSf);
                        float mean1 = (sp[r1*2] + sp[r1*2+1]) * 0.0078125f;
                        float var1  = (sq[r1*2] + sq[r1*2+1]) * 0.0078125f - mean1*mean1;
                        float rs1 = rsqrtf(var1 + EPSf);
                        float* o0 = outp + ((size_t)tile*96 + r0)*128;
                        float* o1 = outp + ((size_t)tile*96 + r1)*128;
                        #pragma unroll
                        for (int ni = 0; ni < 8; ++ni){
                            int n = ncol0 + ni*8 + qcol;
                            float2 g = *(const float2*)(gam + n);
                            float2 b = *(const float2*)(bet + n);
                            float2 oA, oB;
                            oA.x = g.x*(acc[mi*8+ni][0] - mean0)*rs0 + b.x;
                            oA.y = g.y*(acc[mi*8+ni][1] - mean0)*rs0 + b.y;
                            oB.x = g.x*(acc[mi*8+ni][2] - mean1)*rs1 + b.x;
                            oB.y = g.y*(acc[mi*8+ni][3] - mean1)*rs1 + b.y;
                            *(float2*)(o0 + n) = oA;
                            *(float2*)(o1 + n) = oB;
                        }
                    }
                    __syncthreads();
                }
            }
        }
    }
}

// ---------------------------------------------------------------------------
extern "C" void kernel_launch(void* const* d_in, const int* in_sizes, int n_in,
                              void* d_out, int out_size)
{
    const float* hV    = (const float*)d_in[0];
    const float* hE    = (const float*)d_in[1];
    const int*   Eidx  = (const int*)  d_in[2];
    const float* maskV = (const float*)d_in[3];
    const float* maskA = (const float*)d_in[4];
    const float* W1w   = (const float*)d_in[5];  const float* W1b  = (const float*)d_in[6];
    const float* W2w   = (const float*)d_in[7];  const float* W2b  = (const float*)d_in[8];
    const float* W3w   = (const float*)d_in[9];  const float* W3b  = (const float*)d_in[10];
    const float* W11w  = (const float*)d_in[11]; const float* W11b = (const float*)d_in[12];
    const float* W12w  = (const float*)d_in[13]; const float* W12b = (const float*)d_in[14];
    const float* W13w  = (const float*)d_in[15]; const float* W13b = (const float*)d_in[16];
    const float* Winw  = (const float*)d_in[17]; const float* Winb = (const float*)d_in[18];
    const float* Woutw = (const float*)d_in[19]; const float* Woutb= (const float*)d_in[20];
    const float* g1    = (const float*)d_in[21]; const float* b1   = (const float*)d_in[22];
    const float* g2    = (const float*)d_in[23]; const float* b2   = (const float*)d_in[24];
    const float* g3    = (const float*)d_in[25]; const float* b3   = (const float*)d_in[26];

    float* out  = (float*)d_out;
    float* outV = out;
    float* outE = out + (size_t)NODES*Cc;

    float* hV1p; cudaGetSymbolAddress((void**)&hV1p, g_hV1);
    float* hV2p; cudaGetSymbolAddress((void**)&hV2p, g_hV2);
    float* gQp;  cudaGetSymbolAddress((void**)&gQp,  g_Q);
    float* gPp;  cudaGetSymbolAddress((void**)&gPp,  g_P);
    __half* wimg; cudaGetSymbolAddress((void**)&wimg, g_Wimg);

    cudaFuncSetAttribute(prep_w,      cudaFuncAttributeMaxDynamicSharedMemorySize, 65536);
    cudaFuncSetAttribute(node_mma<0>, cudaFuncAttributeMaxDynamicSharedMemorySize, NODE_SMEM);
    cudaFuncSetAttribute(node_mma<1>, cudaFuncAttributeMaxDynamicSharedMemorySize, NODE_SMEM);
    cudaFuncSetAttribute(edge_mma<0>, cudaFuncAttributeMaxDynamicSharedMemorySize, EDGE_SMEM);
    cudaFuncSetAttribute(edge_mma<1>, cudaFuncAttributeMaxDynamicSharedMemorySize, EDGE_SMEM);

    prep_w<<<18, 256, 65536>>>(W1w, W2w, W3w, W11w, W12w, W13w, Winw, Woutw);

    // pass 1: node message
    node_mma<0><<<NODES/16, 128, NODE_SMEM>>>(
        hV, wimg + (size_t)6*32768, wimg + (size_t)7*32768,
        W1b, nullptr, nullptr, nullptr, nullptr, gQp, gPp, nullptr);
    edge_mma<0><<<NODES/4, 192, EDGE_SMEM>>>(
        hE, Eidx, maskA, wimg, W2b, W3b, hV, g1, b1, hV1p);

    // FFN + LN2 + mask
    node_mma<1><<<NODES/16, 128, NODE_SMEM>>>(
        hV1p, wimg + (size_t)10*32768, wimg + (size_t)14*32768,
        Winb, Woutb, g2, b2, maskV, nullptr, nullptr, outV);

    // pass 2: edge update
    node_mma<0><<<NODES/16, 128, NODE_SMEM>>>(
        hV2p, wimg + (size_t)8*32768, wimg + (size_t)9*32768,
        W11b, nullptr, nullptr, nullptr, nullptr, gQp, gPp, nullptr);
    edge_mma<1><<<NODES/4, 192, EDGE_SMEM>>>(
        hE, Eidx, maskA, wimg + (size_t)3*32768, W12b, W13b, hE, g3, b3, outE);
}